// round 12
// baseline (speedup 1.0000x reference)
#include <cuda_runtime.h>
#include <math.h>

#define IMG   512
#define PIX   (IMG * IMG)
#define NIMG  64
#define TX    128
#define RPB   64
#define NITER (RPB + 10)            // 74 streamed rows per block
#define NPAIR (NITER / 2)           // 37 row pairs
#define WCOLS 44                    // 42 used + pad
#define GX    (IMG / TX)            // 4
#define GY    (IMG / RPB)           // 8
#define GZ    (NIMG / 2)            // 32 image pairs (f32x2 packing)
#define NBLK  (GX * GY * GZ)        // 1024

typedef unsigned long long u64;

__device__ double g_part[NBLK];
__device__ int    g_cnt;            // zero-initialized; self-resets each launch

static __device__ __forceinline__ u64 pk2(float a, float b) {
    u64 r; asm("mov.b64 %0, {%1, %2};" : "=l"(r) : "f"(a), "f"(b)); return r;
}
static __device__ __forceinline__ void unpk2(u64 v, float& a, float& b) {
    asm("mov.b64 {%0, %1}, %2;" : "=f"(a), "=f"(b) : "l"(v));
}
static __device__ __forceinline__ u64 f2add(u64 a, u64 b) {
    u64 d; asm("add.rn.f32x2 %0, %1, %2;" : "=l"(d) : "l"(a), "l"(b)); return d;
}
static __device__ __forceinline__ u64 f2sub(u64 a, u64 b) {
    u64 d; asm("sub.rn.f32x2 %0, %1, %2;" : "=l"(d) : "l"(a), "l"(b)); return d;
}
static __device__ __forceinline__ u64 f2mul(u64 a, u64 b) {
    u64 d; asm("mul.rn.f32x2 %0, %1, %2;" : "=l"(d) : "l"(a), "l"(b)); return d;
}
static __device__ __forceinline__ u64 f2fma(u64 a, u64 b, u64 c) {
    u64 d; asm("fma.rn.f32x2 %0, %1, %2, %3;" : "=l"(d) : "l"(a), "l"(b), "l"(c)); return d;
}

__global__ void __launch_bounds__(TX, 3) ssim_main(
    const float* __restrict__ pred, const float* __restrict__ gt,
    float* __restrict__ out)
{
    // R9 base (warp-private tiles, gather vblur) + U/V channel transform:
    //   U = p+g, V = p-g  computed at ingest (LDG shadow).
    // Blurred channels: U, V, U^2, V^2 (squares cost 3 issues/tap vs the
    // 5+3 of the old S/X channels). SSIM recovered via
    //   4 m1 m2      = mU^2 - mV^2
    //   2(m1^2+m2^2) = mU^2 + mV^2
    //   4 blur(pg)   = SU - SV,   2(blur(p^2)+blur(g^2)) = SU + SV
    __shared__ float4 sw[TX / 32][2][2][WCOLS];   // [warp][buf][row][col]
    __shared__ float wred[TX / 32];
    __shared__ int   slast;

    const int tid  = threadIdx.x;
    const int wpid = tid >> 5;
    const int lane = tid & 31;
    const int cx   = blockIdx.x * TX + wpid * 32;   // warp's first output col
    const int ry0  = blockIdx.y * RPB;
    const int im0  = blockIdx.z;

    const float* p0 = pred + (size_t)im0 * PIX;
    const float* p1 = pred + (size_t)(im0 + NIMG / 2) * PIX;
    const float* g0 = gt   + (size_t)im0 * PIX;
    const float* g1 = gt   + (size_t)(im0 + NIMG / 2) * PIX;

    // Gaussian 1D weights (sigma = 11/6, normalized) — same math as reference
    float w[6];
    {
        const float sig = 11.0f / 6.0f;
        const float inv = 1.0f / (2.0f * sig * sig);
        float e[6];
        #pragma unroll
        for (int d = 0; d < 6; ++d) e[d] = expf(-(float)(d * d) * inv);
        float s = e[0] + 2.f * (e[1] + e[2] + e[3] + e[4] + e[5]);
        #pragma unroll
        for (int d = 0; d < 6; ++d) w[d] = e[d] / s;
    }
    u64 w2[6];
    #pragma unroll
    for (int d = 0; d < 6; ++d) w2[d] = pk2(w[d], w[d]);

    const float C1 = 0.01f * 0.01f;
    const float C2 = 0.03f * 0.03f;
    const u64 c1_2  = pk2(C1, C1);
    const u64 c2_2  = pk2(C2, C2);
    const u64 half2 = pk2(0.5f, 0.5f);

    // 11-row ring buffers of horizontally-blurred channels (registers)
    u64 rU[11], rV[11], rUU[11], rVV[11];
    u64 acc0 = 0ull, acc1 = 0ull;

    const int cmain = cx + lane - 5;         // cols cx-5 .. cx+26
    const int chalo = cx + 27 + lane;        // cols cx+27 .. cx+36 (lane<10)
    const bool cm_in = ((unsigned)cmain < IMG);
    const bool ch_in = ((unsigned)chalo < IMG) && (lane < 10);

    // prefetched U/V values (transform applied right after LDG)
    float umA0, umA1, vmA0, vmA1, uhA0, uhA1, vhA0, vhA1;
    float umB0, umB1, vmB0, vmB1, uhB0, uhB1, vhB0, vhB1;

    #define LOADROW(sfx, T)                                                     \
        {                                                                       \
            const int yin = ry0 - 5 + (T);                                      \
            const bool rok = ((unsigned)yin < IMG);                             \
            const bool ok  = rok && cm_in;                                      \
            const int off = yin * IMG + cmain;                                  \
            float pa = ok ? p0[off] : 0.f;  float pb = ok ? p1[off] : 0.f;      \
            float ga = ok ? g0[off] : 0.f;  float gb = ok ? g1[off] : 0.f;      \
            um##sfx##0 = pa + ga;  vm##sfx##0 = pa - ga;                        \
            um##sfx##1 = pb + gb;  vm##sfx##1 = pb - gb;                        \
            const bool ok2 = rok && ch_in;                                      \
            const int off2 = yin * IMG + chalo;                                 \
            float ha = ok2 ? p0[off2] : 0.f;  float hb = ok2 ? p1[off2] : 0.f;  \
            float ia = ok2 ? g0[off2] : 0.f;  float ib = ok2 ? g1[off2] : 0.f;  \
            uh##sfx##0 = ha + ia;  vh##sfx##0 = ha - ia;                        \
            uh##sfx##1 = hb + ib;  vh##sfx##1 = hb - ib;                        \
        }

    LOADROW(A, 0)
    LOADROW(B, 1)

    for (int outer = 0; outer < 4; ++outer) {
        #pragma unroll
        for (int j = 0; j < 11; ++j) {
            const int pair = outer * 11 + j;
            if (pair < NPAIR) {
                const int buf = pair & 1;
                // ---- store both transformed rows into warp-private window ----
                sw[wpid][buf][0][lane] = make_float4(umA0, umA1, vmA0, vmA1);
                sw[wpid][buf][1][lane] = make_float4(umB0, umB1, vmB0, vmB1);
                if (lane < 10) {
                    sw[wpid][buf][0][32 + lane] = make_float4(uhA0, uhA1, vhA0, vhA1);
                    sw[wpid][buf][1][32 + lane] = make_float4(uhB0, uhB1, vhB0, vhB1);
                }
                // ---- prefetch next pair (warp-local; no block barrier) ----
                const int t0 = 2 * pair;
                if (t0 + 2 < NITER) LOADROW(A, t0 + 2)
                if (t0 + 3 < NITER) LOADROW(B, t0 + 3)
                __syncwarp();

                const int k0 = (2 * j) % 11;
                const int k1 = (2 * j + 1) % 11;
                #define HBLUR(ROW, KD)                                                      \
                    {                                                                       \
                        const float4* Vv = &sw[wpid][buf][ROW][lane];                       \
                        float4 cv = Vv[5];                                                  \
                        u64 uc = pk2(cv.x, cv.y), vc = pk2(cv.z, cv.w);                     \
                        u64 hU  = f2mul(uc, w2[0]);                                         \
                        u64 hV  = f2mul(vc, w2[0]);                                         \
                        u64 hUU = f2mul(f2mul(uc, uc), w2[0]);                              \
                        u64 hVV = f2mul(f2mul(vc, vc), w2[0]);                              \
                        _Pragma("unroll")                                                   \
                        for (int d = 1; d <= 5; ++d) {                                      \
                            float4 Lv = Vv[5 - d], Rv = Vv[5 + d];                          \
                            u64 ul = pk2(Lv.x, Lv.y), vl = pk2(Lv.z, Lv.w);                 \
                            u64 ur = pk2(Rv.x, Rv.y), vr = pk2(Rv.z, Rv.w);                 \
                            hU  = f2fma(f2add(ul, ur), w2[d], hU);                          \
                            hV  = f2fma(f2add(vl, vr), w2[d], hV);                          \
                            hUU = f2fma(f2fma(ur, ur, f2mul(ul, ul)), w2[d], hUU);          \
                            hVV = f2fma(f2fma(vr, vr, f2mul(vl, vl)), w2[d], hVV);          \
                        }                                                                   \
                        rU[KD] = hU; rV[KD] = hV; rUU[KD] = hUU; rVV[KD] = hVV;             \
                    }
                HBLUR(0, k0)
                HBLUR(1, k1)
                #undef HBLUR

                if (pair >= 5) {
                    #define VS(K, JJ) (((K) + 6 + (JJ) + 11) % 11)
                    #define VBLUR(dst, r, K)                                           \
                        { u64 pa = f2fma(f2add(r[VS(K,-1)], r[VS(K,1)]), w2[1],        \
                                         f2mul(r[VS(K,0)], w2[0]));                    \
                          pa = f2fma(f2add(r[VS(K,-3)], r[VS(K,3)]), w2[3], pa);       \
                          u64 pb = f2mul(f2add(r[VS(K,-2)], r[VS(K,2)]), w2[2]);       \
                          pb = f2fma(f2add(r[VS(K,-4)], r[VS(K,4)]), w2[4], pb);       \
                          pb = f2fma(f2add(r[VS(K,-5)], r[VS(K,5)]), w2[5], pb);       \
                          dst = f2add(pa, pb); }
                    #define SSIMROW(K, ACC)                                            \
                        { u64 mU, mV, SU, SV;                                          \
                          VBLUR(mU, rU,  K); VBLUR(mV, rV,  K);                        \
                          VBLUR(SU, rUU, K); VBLUR(SV, rVV, K);                        \
                          u64 t1 = f2mul(mU, mU);                                      \
                          u64 t2 = f2mul(mV, mV);                                      \
                          u64 dm = f2sub(t1, t2);       /* 4 m1 m2            */       \
                          u64 sm = f2add(t1, t2);       /* 2(m1^2+m2^2)       */       \
                          u64 A  = f2fma(dm, half2, c1_2);                             \
                          u64 Cq = f2fma(sm, half2, c1_2);                             \
                          u64 e  = f2sub(f2sub(SU, SV), dm);   /* 4 sigma12 *2 */      \
                          u64 f_ = f2sub(f2add(SU, SV), sm);   /* 2(sig1+sig2) */      \
                          u64 B  = f2fma(e,  half2, c2_2);                             \
                          u64 Dq = f2fma(f_, half2, c2_2);                             \
                          u64 num = f2mul(A, B);                                       \
                          u64 den = f2mul(Cq, Dq);                                     \
                          float na, nb, da, db;                                        \
                          unpk2(num, na, nb); unpk2(den, da, db);                      \
                          ACC = f2add(ACC, pk2(__fdividef(na, da),                     \
                                               __fdividef(nb, db))); }
                    SSIMROW(k0, acc0)
                    SSIMROW(k1, acc1)
                    #undef SSIMROW
                    #undef VBLUR
                    #undef VS
                }
            }
        }
    }
    #undef LOADROW

    // ---- block reduction (deterministic partials, no float atomics) ----
    u64 accT = f2add(acc0, acc1);
    float a0, a1; unpk2(accT, a0, a1);
    float s = a0 + a1;
    #pragma unroll
    for (int o = 16; o > 0; o >>= 1) s += __shfl_xor_sync(0xffffffffu, s, o);
    if (lane == 0) wred[wpid] = s;
    __syncthreads();
    if (tid == 0) {
        double bs = 0.0;
        #pragma unroll
        for (int i = 0; i < TX / 32; ++i) bs += (double)wred[i];
        const int bid = blockIdx.x + GX * (blockIdx.y + GY * blockIdx.z);
        g_part[bid] = bs;
        __threadfence();
        int old = atomicAdd(&g_cnt, 1);
        slast = (old == NBLK - 1) ? 1 : 0;
    }
    __syncthreads();

    // ---- last block finalizes (deterministic fixed-order double sum) ----
    if (slast) {
        __threadfence();
        double v = 0.0;
        #pragma unroll
        for (int i = 0; i < NBLK / TX; ++i)
            v += g_part[tid + i * TX];
        #pragma unroll
        for (int o = 16; o > 0; o >>= 1) v += __shfl_xor_sync(0xffffffffu, v, o);
        __shared__ double sh[TX / 32];
        if ((tid & 31) == 0) sh[tid >> 5] = v;
        __syncthreads();
        if (tid == 0) {
            double tot = 0.0;
            #pragma unroll
            for (int i = 0; i < TX / 32; ++i) tot += sh[i];
            out[0] = (float)(1.0 - tot / ((double)NIMG * (double)PIX));
            g_cnt = 0;   // self-reset for graph replay
        }
    }
}

extern "C" void kernel_launch(void* const* d_in, const int* in_sizes, int n_in,
                              void* d_out, int out_size)
{
    const float* pred = (const float*)d_in[0];
    const float* gt   = (const float*)d_in[1];
    float* out = (float*)d_out;

    dim3 grid(GX, GY, GZ);
    ssim_main<<<grid, TX>>>(pred, gt, out);
}

// round 13
// speedup vs baseline: 1.1686x; 1.1686x over previous
#include <cuda_runtime.h>
#include <math.h>

#define IMG   512
#define PIX   (IMG * IMG)
#define NIMG  64
#define TX    128
#define RPB   64
#define NITER (RPB + 10)            // 74 streamed rows per block
#define NPAIR (NITER / 2)           // 37 row pairs
#define WCOLS 44                    // 42 used + pad
#define GX    (IMG / TX)            // 4
#define GY    (IMG / RPB)           // 8
#define GZ    (NIMG / 2)            // 32 image pairs (f32x2 packing)
#define NBLK  (GX * GY * GZ)        // 1024

typedef unsigned long long u64;

__device__ double g_part[NBLK];
__device__ int    g_cnt;            // zero-initialized; self-resets each launch

static __device__ __forceinline__ u64 pk2(float a, float b) {
    u64 r; asm("mov.b64 %0, {%1, %2};" : "=l"(r) : "f"(a), "f"(b)); return r;
}
static __device__ __forceinline__ void unpk2(u64 v, float& a, float& b) {
    asm("mov.b64 {%0, %1}, %2;" : "=f"(a), "=f"(b) : "l"(v));
}
static __device__ __forceinline__ u64 f2add(u64 a, u64 b) {
    u64 d; asm("add.rn.f32x2 %0, %1, %2;" : "=l"(d) : "l"(a), "l"(b)); return d;
}
static __device__ __forceinline__ u64 f2sub(u64 a, u64 b) {
    u64 d; asm("sub.rn.f32x2 %0, %1, %2;" : "=l"(d) : "l"(a), "l"(b)); return d;
}
static __device__ __forceinline__ u64 f2mul(u64 a, u64 b) {
    u64 d; asm("mul.rn.f32x2 %0, %1, %2;" : "=l"(d) : "l"(a), "l"(b)); return d;
}
static __device__ __forceinline__ u64 f2fma(u64 a, u64 b, u64 c) {
    u64 d; asm("fma.rn.f32x2 %0, %1, %2, %3;" : "=l"(d) : "l"(a), "l"(b), "l"(c)); return d;
}

__global__ void __launch_bounds__(TX, 3) ssim_main(
    const float* __restrict__ pred, const float* __restrict__ gt,
    float* __restrict__ out)
{
    // R9 skeleton (raw p/g prefetch regs, warp-private tiles, gather vblur)
    // with the U/V transform applied TRANSIENTLY at STS time (R4 pattern):
    //   tile stores (u0, u1, v0, v1) where u = p+g, v = p-g.
    // Blur channels U, V, U^2, V^2 (3 issues/tap each; saves 12 packed
    // issues/row vs p,g,p^2+g^2,pg). SSIM recovered via:
    //   4 m1 m2 = mU^2 - mV^2        2(m1^2+m2^2) = mU^2 + mV^2
    //   2(2 sigma12 + dm-term): SU - SV - dm      2(sig1+sig2): SU + SV - sm
    __shared__ float4 sw[TX / 32][2][2][WCOLS];   // [warp][buf][row][col]
    __shared__ float wred[TX / 32];
    __shared__ int   slast;

    const int tid  = threadIdx.x;
    const int wpid = tid >> 5;
    const int lane = tid & 31;
    const int cx   = blockIdx.x * TX + wpid * 32;   // warp's first output col
    const int ry0  = blockIdx.y * RPB;
    const int im0  = blockIdx.z;

    const float* p0 = pred + (size_t)im0 * PIX;
    const float* p1 = pred + (size_t)(im0 + NIMG / 2) * PIX;
    const float* g0 = gt   + (size_t)im0 * PIX;
    const float* g1 = gt   + (size_t)(im0 + NIMG / 2) * PIX;

    // Gaussian 1D weights (sigma = 11/6, normalized) — same math as reference
    float w[6];
    {
        const float sig = 11.0f / 6.0f;
        const float inv = 1.0f / (2.0f * sig * sig);
        float e[6];
        #pragma unroll
        for (int d = 0; d < 6; ++d) e[d] = expf(-(float)(d * d) * inv);
        float s = e[0] + 2.f * (e[1] + e[2] + e[3] + e[4] + e[5]);
        #pragma unroll
        for (int d = 0; d < 6; ++d) w[d] = e[d] / s;
    }
    u64 w2[6];
    #pragma unroll
    for (int d = 0; d < 6; ++d) w2[d] = pk2(w[d], w[d]);

    const float C1 = 0.01f * 0.01f;
    const float C2 = 0.03f * 0.03f;
    const u64 c1_2  = pk2(C1, C1);
    const u64 c2_2  = pk2(C2, C2);
    const u64 half2 = pk2(0.5f, 0.5f);

    // 11-row ring buffers of horizontally-blurred channels (registers)
    u64 rU[11], rV[11], rUU[11], rVV[11];
    u64 acc0 = 0ull, acc1 = 0ull;

    const int cmain = cx + lane - 5;         // cols cx-5 .. cx+26
    const int chalo = cx + 27 + lane;        // cols cx+27 .. cx+36 (lane<10)
    const bool cm_in = ((unsigned)cmain < IMG);
    const bool ch_in = ((unsigned)chalo < IMG) && (lane < 10);

    // prefetch register sets: RAW p/g values (exactly as R9)
    float pmA0, pmA1, gmA0, gmA1, phA0, phA1, ghA0, ghA1;
    float pmB0, pmB1, gmB0, gmB1, phB0, phB1, ghB0, ghB1;

    #define LOADROW(sfx, T)                                                     \
        {                                                                       \
            const int yin = ry0 - 5 + (T);                                      \
            const bool rok = ((unsigned)yin < IMG);                             \
            const bool ok  = rok && cm_in;                                      \
            const int off = yin * IMG + cmain;                                  \
            pm##sfx##0 = ok ? p0[off] : 0.f;  pm##sfx##1 = ok ? p1[off] : 0.f;  \
            gm##sfx##0 = ok ? g0[off] : 0.f;  gm##sfx##1 = ok ? g1[off] : 0.f;  \
            const bool ok2 = rok && ch_in;                                      \
            const int off2 = yin * IMG + chalo;                                 \
            ph##sfx##0 = ok2 ? p0[off2] : 0.f; ph##sfx##1 = ok2 ? p1[off2] : 0.f;\
            gh##sfx##0 = ok2 ? g0[off2] : 0.f; gh##sfx##1 = ok2 ? g1[off2] : 0.f;\
        }

    LOADROW(A, 0)
    LOADROW(B, 1)

    for (int outer = 0; outer < 4; ++outer) {
        #pragma unroll
        for (int j = 0; j < 11; ++j) {
            const int pair = outer * 11 + j;
            if (pair < NPAIR) {
                const int buf = pair & 1;
                // ---- store both rows, transformed TRANSIENTLY at STS ----
                sw[wpid][buf][0][lane] = make_float4(pmA0 + gmA0, pmA1 + gmA1,
                                                     pmA0 - gmA0, pmA1 - gmA1);
                sw[wpid][buf][1][lane] = make_float4(pmB0 + gmB0, pmB1 + gmB1,
                                                     pmB0 - gmB0, pmB1 - gmB1);
                if (lane < 10) {
                    sw[wpid][buf][0][32 + lane] = make_float4(phA0 + ghA0, phA1 + ghA1,
                                                              phA0 - ghA0, phA1 - ghA1);
                    sw[wpid][buf][1][32 + lane] = make_float4(phB0 + ghB0, phB1 + ghB1,
                                                              phB0 - ghB0, phB1 - ghB1);
                }
                // ---- prefetch next pair (warp-local; no block barrier) ----
                const int t0 = 2 * pair;
                if (t0 + 2 < NITER) LOADROW(A, t0 + 2)
                if (t0 + 3 < NITER) LOADROW(B, t0 + 3)
                __syncwarp();

                const int k0 = (2 * j) % 11;
                const int k1 = (2 * j + 1) % 11;
                #define HBLUR(ROW, KD)                                                      \
                    {                                                                       \
                        const float4* Vv = &sw[wpid][buf][ROW][lane];                       \
                        float4 cv = Vv[5];                                                  \
                        u64 uc = pk2(cv.x, cv.y), vc = pk2(cv.z, cv.w);                     \
                        u64 hU  = f2mul(uc, w2[0]);                                         \
                        u64 hV  = f2mul(vc, w2[0]);                                         \
                        u64 hUU = f2mul(f2mul(uc, uc), w2[0]);                              \
                        u64 hVV = f2mul(f2mul(vc, vc), w2[0]);                              \
                        _Pragma("unroll")                                                   \
                        for (int d = 1; d <= 5; ++d) {                                      \
                            float4 Lv = Vv[5 - d], Rv = Vv[5 + d];                          \
                            u64 ul = pk2(Lv.x, Lv.y), vl = pk2(Lv.z, Lv.w);                 \
                            u64 ur = pk2(Rv.x, Rv.y), vr = pk2(Rv.z, Rv.w);                 \
                            hU  = f2fma(f2add(ul, ur), w2[d], hU);                          \
                            hV  = f2fma(f2add(vl, vr), w2[d], hV);                          \
                            hUU = f2fma(f2fma(ur, ur, f2mul(ul, ul)), w2[d], hUU);          \
                            hVV = f2fma(f2fma(vr, vr, f2mul(vl, vl)), w2[d], hVV);          \
                        }                                                                   \
                        rU[KD] = hU; rV[KD] = hV; rUU[KD] = hUU; rVV[KD] = hVV;             \
                    }
                HBLUR(0, k0)
                HBLUR(1, k1)
                #undef HBLUR

                if (pair >= 5) {
                    #define VS(K, JJ) (((K) + 6 + (JJ) + 11) % 11)
                    #define VBLUR(dst, r, K)                                           \
                        { u64 pa = f2fma(f2add(r[VS(K,-1)], r[VS(K,1)]), w2[1],        \
                                         f2mul(r[VS(K,0)], w2[0]));                    \
                          pa = f2fma(f2add(r[VS(K,-3)], r[VS(K,3)]), w2[3], pa);       \
                          u64 pb = f2mul(f2add(r[VS(K,-2)], r[VS(K,2)]), w2[2]);       \
                          pb = f2fma(f2add(r[VS(K,-4)], r[VS(K,4)]), w2[4], pb);       \
                          pb = f2fma(f2add(r[VS(K,-5)], r[VS(K,5)]), w2[5], pb);       \
                          dst = f2add(pa, pb); }
                    // tight epilogue: reuse temps to cap live u64 count
                    #define SSIMROW(K, ACC)                                            \
                        { u64 mU, mV, SU, SV;                                          \
                          VBLUR(mU, rU,  K); VBLUR(mV, rV,  K);                        \
                          VBLUR(SU, rUU, K); VBLUR(SV, rVV, K);                        \
                          u64 t1 = f2mul(mU, mU);                                      \
                          u64 t2 = f2mul(mV, mV);                                      \
                          u64 dm = f2sub(t1, t2);          /* 4 m1 m2 */               \
                          u64 sm = f2add(t1, t2);          /* 2(m1^2+m2^2) */          \
                          t1 = f2fma(dm, half2, c1_2);     /* A  */                    \
                          t2 = f2fma(f2sub(f2sub(SU, SV), dm), half2, c2_2); /* B */   \
                          u64 num = f2mul(t1, t2);                                     \
                          t1 = f2fma(sm, half2, c1_2);     /* Cq */                    \
                          t2 = f2fma(f2sub(f2add(SU, SV), sm), half2, c2_2); /* Dq */  \
                          u64 den = f2mul(t1, t2);                                     \
                          float na, nb, da, db;                                        \
                          unpk2(num, na, nb); unpk2(den, da, db);                      \
                          ACC = f2add(ACC, pk2(__fdividef(na, da),                     \
                                               __fdividef(nb, db))); }
                    SSIMROW(k0, acc0)
                    SSIMROW(k1, acc1)
                    #undef SSIMROW
                    #undef VBLUR
                    #undef VS
                }
            }
        }
    }
    #undef LOADROW

    // ---- block reduction (deterministic partials, no float atomics) ----
    u64 accT = f2add(acc0, acc1);
    float a0, a1; unpk2(accT, a0, a1);
    float s = a0 + a1;
    #pragma unroll
    for (int o = 16; o > 0; o >>= 1) s += __shfl_xor_sync(0xffffffffu, s, o);
    if (lane == 0) wred[wpid] = s;
    __syncthreads();
    if (tid == 0) {
        double bs = 0.0;
        #pragma unroll
        for (int i = 0; i < TX / 32; ++i) bs += (double)wred[i];
        const int bid = blockIdx.x + GX * (blockIdx.y + GY * blockIdx.z);
        g_part[bid] = bs;
        __threadfence();
        int old = atomicAdd(&g_cnt, 1);
        slast = (old == NBLK - 1) ? 1 : 0;
    }
    __syncthreads();

    // ---- last block finalizes (deterministic fixed-order double sum) ----
    if (slast) {
        __threadfence();
        double v = 0.0;
        #pragma unroll
        for (int i = 0; i < NBLK / TX; ++i)
            v += g_part[tid + i * TX];
        #pragma unroll
        for (int o = 16; o > 0; o >>= 1) v += __shfl_xor_sync(0xffffffffu, v, o);
        __shared__ double sh[TX / 32];
        if ((tid & 31) == 0) sh[tid >> 5] = v;
        __syncthreads();
        if (tid == 0) {
            double tot = 0.0;
            #pragma unroll
            for (int i = 0; i < TX / 32; ++i) tot += sh[i];
            out[0] = (float)(1.0 - tot / ((double)NIMG * (double)PIX));
            g_cnt = 0;   // self-reset for graph replay
        }
    }
}

extern "C" void kernel_launch(void* const* d_in, const int* in_sizes, int n_in,
                              void* d_out, int out_size)
{
    const float* pred = (const float*)d_in[0];
    const float* gt   = (const float*)d_in[1];
    float* out = (float*)d_out;

    dim3 grid(GX, GY, GZ);
    ssim_main<<<grid, TX>>>(pred, gt, out);
}